// round 11
// baseline (speedup 1.0000x reference)
#include <cuda_runtime.h>
#include <float.h>
#include <stdint.h>

// ROI max pooling, SINGLE kernel, cp.async-pipelined.
// feat: [B=8, H=50, W=50, C=256] fp32 NHWC; rois: [N,5] (img,x1,y1,x2,y2) incl.
// Dataset ROIs are 28x28 with 7x7 pooling -> each bin = aligned 4x4 window at
// (y1+4br, x1+4bc). 4x4 tiles partition the 47x47 window-origin grid; each
// tile CTA streams its 7 input rows gmem->smem via cp.async (3-slot ring),
// computes the 4x4 window maxes in registers, parks them in smem, scans the
// ROI list for consumers, and scatters to out.
// Extra per-ROI CTAs handle any non-28x28 ROI via the general path.

#define FH 50
#define FW 50
#define CCH 256
#define PH 7
#define PW 7
#define NXC 12                   // tiles per row: ceil(47/4)
#define NYC 12
#define NTILES (8 * NYC * NXC)   // 1152
#define MAXM 256                 // match-list capacity per tile
#define SLOT_FLOATS (7 * CCH)    // 1792 floats = 7168 B per ring slot

__device__ __forceinline__ float2 fmax2(float2 a, float2 b) {
    float2 r;
    r.x = fmaxf(a.x, b.x);
    r.y = fmaxf(a.y, b.y);
    return r;
}

__device__ __forceinline__ void cp16(uint32_t dst_smem, const void* src) {
    asm volatile("cp.async.cg.shared.global [%0], [%1], 16;"
                 :: "r"(dst_smem), "l"(src));
}
__device__ __forceinline__ void cp_commit() {
    asm volatile("cp.async.commit_group;");
}
template <int N>
__device__ __forceinline__ void cp_wait() {
    asm volatile("cp.async.wait_group %0;" :: "n"(N));
}

__global__ __launch_bounds__(128, 8)
void roi_pool_fused(const float* __restrict__ feat,
                    const int*   __restrict__ rois,
                    float*       __restrict__ out,
                    int n_rois)
{
    const int tid  = threadIdx.x;        // 0..127
    const int coff = tid * 2;            // 2 channels per thread

    // ---------- fallback CTAs: one per ROI, only act on non-28x28 ----------
    if (blockIdx.x >= NTILES) {
        const int roi = blockIdx.x - NTILES;
        if (roi >= n_rois) return;
        const int* r = rois + roi * 5;
        const int img = r[0], x1 = r[1], y1 = r[2], x2 = r[3], y2 = r[4];
        const int roi_h = y2 - y1 + 1;
        const int roi_w = x2 - x1 + 1;
        if (roi_h == 28 && roi_w == 28) return;   // handled by tile CTAs

        const float* base = feat
            + (((size_t)img * FH + (size_t)y1) * FW + (size_t)x1) * CCH + coff;
        for (int br = 0; br < PH; ++br) {
            const int rs = (br * roi_h + PH - 1) / PH;
            const int re = (br == PH - 1) ? roi_h
                                          : ((br + 1) * roi_h + PH - 1) / PH;
            for (int bc = 0; bc < PW; ++bc) {
                const int cs = (bc * roi_w + PW - 1) / PW;
                const int ce = (bc == PW - 1) ? roi_w
                                              : ((bc + 1) * roi_w + PW - 1) / PW;
                float2 m = make_float2(-FLT_MAX, -FLT_MAX);
                for (int y = rs; y < re; ++y) {
                    const float* rowp = base + (size_t)y * (FW * CCH);
                    for (int x = cs; x < ce; ++x) {
                        const float2 v =
                            *reinterpret_cast<const float2*>(rowp + (size_t)x * CCH);
                        m = fmax2(m, v);
                    }
                }
                *reinterpret_cast<float2*>(
                    out + ((size_t)((roi * PH + br) * PW + bc)) * CCH + coff) = m;
            }
        }
        return;
    }

    // ---------------------- tile CTAs ----------------------
    __shared__ __align__(16) float s_ring[3 * SLOT_FLOATS];   // 21504 B
    __shared__ int s_roi[MAXM];
    __shared__ int s_pk[MAXM];
    __shared__ int s_cnt;

    const int id = blockIdx.x;           // ((b*NYC)+ty)*NXC + tx
    const int tx = id % NXC;
    const int t1 = id / NXC;
    const int ty = t1 % NYC;
    const int b  = t1 / NYC;
    const int x0 = tx * 4;
    const int y0 = ty * 4;

    if (tid == 0) s_cnt = 0;

    const int npix = min(7, FW - x0);    // valid pixels per row
    const int nq   = npix * (CCH / 4);   // float4 chunks per row
    const uint32_t ring_u32 =
        (uint32_t)__cvta_generic_to_shared(s_ring);

    // Issue one row's gmem->smem copy (or an empty group if row is OOB).
    #define ISSUE_ROW(J)                                                      \
    do {                                                                      \
        const int _y = y0 + (J);                                              \
        if (_y < FH) {                                                        \
            const float4* _src = reinterpret_cast<const float4*>(             \
                feat + (((size_t)b * FH + _y) * FW + x0) * CCH);              \
            const uint32_t _dst = ring_u32 + ((J) % 3) * (SLOT_FLOATS * 4);   \
            for (int _i = tid; _i < nq; _i += 128)                            \
                cp16(_dst + _i * 16, _src + _i);                              \
        }                                                                     \
        cp_commit();                                                          \
    } while (0)

    ISSUE_ROW(0);
    ISSUE_ROW(1);

    const float2 NEG = make_float2(-FLT_MAX, -FLT_MAX);
    float2 acc[4][4];
    #pragma unroll
    for (int r = 0; r < 4; ++r)
        #pragma unroll
        for (int c = 0; c < 4; ++c)
            acc[r][c] = NEG;

    #pragma unroll
    for (int j = 0; j < 7; ++j) {
        if (j < 6) cp_wait<1>(); else cp_wait<0>();
        __syncthreads();                 // row j visible to all threads

        const float* slot = s_ring + (j % 3) * SLOT_FLOATS + coff;
        float2 v[7];
        #pragma unroll
        for (int k = 0; k < 7; ++k)
            v[k] = *reinterpret_cast<const float2*>(slot + k * CCH);

        const float2 m01 = fmax2(v[0], v[1]);
        const float2 m12 = fmax2(v[1], v[2]);
        const float2 m23 = fmax2(v[2], v[3]);
        const float2 m34 = fmax2(v[3], v[4]);
        const float2 m45 = fmax2(v[4], v[5]);
        const float2 m56 = fmax2(v[5], v[6]);
        float2 h[4];
        h[0] = fmax2(m01, m23);
        h[1] = fmax2(m12, m34);
        h[2] = fmax2(m23, m45);
        h[3] = fmax2(m34, m56);

        #pragma unroll
        for (int r = 0; r < 4; ++r)
            if (j >= r && j <= r + 3)
                #pragma unroll
                for (int c = 0; c < 4; ++c)
                    acc[r][c] = fmax2(acc[r][c], h[c]);

        // refill the slot all threads finished reading one iteration ago
        if (j + 2 < 7) ISSUE_ROW(j + 2);
    }

    __syncthreads();                     // all compute done; ring reusable

    // Park finished tile (16 KB) into the ring region for dynamic indexing.
    float2* park = reinterpret_cast<float2*>(s_ring);
    #pragma unroll
    for (int r = 0; r < 4; ++r)
        #pragma unroll
        for (int c = 0; c < 4; ++c)
            park[(r * 4 + c) * 128 + tid] = acc[r][c];

    __syncthreads();                     // park visible; s_cnt=0 long ordered

    // Scan ROIs; each thread handles rois tid, tid+128, ...
    for (int roi = tid; roi < n_rois; roi += 128) {
        const int* r = rois + roi * 5;
        const int img = r[0], x1 = r[1], y1 = r[2], x2 = r[3], y2 = r[4];
        if (img != b) continue;
        if (y2 - y1 != 27 || x2 - x1 != 27) continue;  // fallback CTA handles
        const int dy = y0 - y1;
        const int dx = x0 - x1;
        if (dy < -3 || dy > 24 || dx < -3 || dx > 24) continue;
        const int br = (dy + 3) >> 2;      // unique bin row landing in tile
        const int bc = (dx + 3) >> 2;
        const int yloc = 4 * br - dy;      // 0..3
        const int xloc = 4 * bc - dx;      // 0..3
        const int slot = atomicAdd(&s_cnt, 1);
        if (slot < MAXM) {
            s_roi[slot] = roi;
            s_pk[slot]  = (br << 12) | (bc << 8) | (yloc << 4) | xloc;
        }
    }

    __syncthreads();

    // Scatter: every thread writes its 2 channels for each match.
    const int cnt = min(s_cnt, MAXM);
    for (int i = 0; i < cnt; ++i) {
        const int roi = s_roi[i];
        const int pk  = s_pk[i];
        const int br   = (pk >> 12) & 0xF;
        const int bc   = (pk >> 8)  & 0xF;
        const int yloc = (pk >> 4)  & 0xF;
        const int xloc =  pk        & 0xF;
        *reinterpret_cast<float2*>(
            out + ((size_t)((roi * PH + br) * PW + bc)) * CCH + coff)
            = park[(yloc * 4 + xloc) * 128 + tid];
    }
}

extern "C" void kernel_launch(void* const* d_in, const int* in_sizes, int n_in,
                              void* d_out, int out_size)
{
    const float* feat = (const float*)d_in[0];
    const int*   rois = (const int*)d_in[1];
    const int n_rois = in_sizes[1] / 5;
    float* out = (float*)d_out;

    roi_pool_fused<<<NTILES + n_rois, 128>>>(feat, rois, out, n_rois);
}